// round 2
// baseline (speedup 1.0000x reference)
#include <cuda_runtime.h>
#include <cuda_bf16.h>
#include <math.h>

// Problem constants
#define B_ 2
#define L_ 2048
#define DIM_ 1024
#define DIN_ 2048
#define NSTATE 16
#define DTR_ 64
#define TOKENS (B_ * L_)   // 4096

// Scratch buffers (allocation-free: __device__ globals)
__device__ float g_xs[TOKENS * DIN_];     // conv input
__device__ float g_gate[TOKENS * DIN_];   // silu(res)
__device__ float g_u[TOKENS * DIN_];      // silu(conv(xs))
__device__ float g_xdbl[TOKENS * 96];     // u @ W_x
__device__ float g_delta[TOKENS * DIN_];  // softplus(...)
__device__ float g_ys[TOKENS * DIN_];     // scan output * gate

// ---------------------------------------------------------------------------
// Generic tiled FP32 GEMM: C[M,N] = A[M,K] @ B[K,N], row-major with ld params.
// BM=BN=64, BK=16, 256 threads, 4x4 per thread.
// EPI: 0 = plain store, 1 = split (cols<DIN -> C0, else silu -> C1),
//      2 = +bias then softplus -> C0
// ---------------------------------------------------------------------------
template <int EPI>
__global__ void gemm64(const float* __restrict__ A, int lda,
                       const float* __restrict__ B, int ldb,
                       int M, int N, int K,
                       const float* __restrict__ bias,
                       float* __restrict__ C0, float* __restrict__ C1, int ldc)
{
    constexpr int BM = 64, BN = 64, BK = 16;
    __shared__ __align__(16) float As[BK][BM];
    __shared__ __align__(16) float Bs[BK][BN];

    const int tid = threadIdx.x;
    const int block_row = blockIdx.y * BM;
    const int block_col = blockIdx.x * BN;

    // A tile load map: 64 rows x 16 k -> each thread one float4 along K
    const int a_row  = tid >> 2;          // 0..63
    const int a_col4 = (tid & 3) << 2;    // 0,4,8,12
    // B tile load map: 16 k x 64 cols -> each thread one float4 along N
    const int b_row  = tid >> 4;          // 0..15
    const int b_col4 = (tid & 15) << 2;   // 0..60

    const int ty = tid >> 4;   // 0..15 -> rows ty*4..+3
    const int tx = tid & 15;   // 0..15 -> cols tx*4..+3

    float acc[4][4];
#pragma unroll
    for (int i = 0; i < 4; i++)
#pragma unroll
        for (int j = 0; j < 4; j++) acc[i][j] = 0.f;

    for (int k0 = 0; k0 < K; k0 += BK) {
        // Load A fragment (M,K dims always tile-aligned in this problem)
        float4 av = *reinterpret_cast<const float4*>(
            &A[(size_t)(block_row + a_row) * lda + k0 + a_col4]);
        As[a_col4 + 0][a_row] = av.x;
        As[a_col4 + 1][a_row] = av.y;
        As[a_col4 + 2][a_row] = av.z;
        As[a_col4 + 3][a_row] = av.w;

        // Load B fragment with N guard (N=96 case)
        float4 bv = make_float4(0.f, 0.f, 0.f, 0.f);
        const int gcol = block_col + b_col4;
        if (gcol < N)
            bv = *reinterpret_cast<const float4*>(
                &B[(size_t)(k0 + b_row) * ldb + gcol]);
        *reinterpret_cast<float4*>(&Bs[b_row][b_col4]) = bv;

        __syncthreads();

#pragma unroll
        for (int k = 0; k < BK; k++) {
            const float4 a4 = *reinterpret_cast<const float4*>(&As[k][ty << 2]);
            const float4 b4 = *reinterpret_cast<const float4*>(&Bs[k][tx << 2]);
            const float ar[4] = {a4.x, a4.y, a4.z, a4.w};
            const float br[4] = {b4.x, b4.y, b4.z, b4.w};
#pragma unroll
            for (int i = 0; i < 4; i++)
#pragma unroll
                for (int j = 0; j < 4; j++)
                    acc[i][j] = fmaf(ar[i], br[j], acc[i][j]);
        }
        __syncthreads();
    }

#pragma unroll
    for (int i = 0; i < 4; i++) {
        const int row = block_row + (ty << 2) + i;
#pragma unroll
        for (int j = 0; j < 4; j++) {
            const int col = block_col + (tx << 2) + j;
            if (col >= N) continue;
            const float v = acc[i][j];
            if (EPI == 0) {
                C0[(size_t)row * ldc + col] = v;
            } else if (EPI == 1) {
                if (col < DIN_) {
                    C0[(size_t)row * DIN_ + col] = v;
                } else {
                    // silu(res)
                    C1[(size_t)row * DIN_ + (col - DIN_)] =
                        v / (1.f + __expf(-v));
                }
            } else { // EPI == 2: bias + softplus
                const float t = v + bias[col];
                C0[(size_t)row * ldc + col] =
                    (t > 20.f) ? t : log1pf(__expf(t));
            }
        }
    }
}

// ---------------------------------------------------------------------------
// Depthwise causal conv1d (k=4) + bias + SiLU. One thread per (token, channel).
// ---------------------------------------------------------------------------
__global__ void conv_silu_kernel(const float* __restrict__ xs,
                                 const float* __restrict__ w,
                                 const float* __restrict__ bias,
                                 float* __restrict__ u)
{
    const int idx = blockIdx.x * blockDim.x + threadIdx.x; // token*DIN + c
    const int c = idx & (DIN_ - 1);
    const int t = idx >> 11;          // token (DIN_ = 2048 = 1<<11)
    const int l = t & (L_ - 1);       // position within sequence
    float acc = bias[c];
#pragma unroll
    for (int k = 0; k < 4; k++) {
        const int lp = l - 3 + k;
        if (lp >= 0)
            acc = fmaf(xs[(size_t)(t - l + lp) * DIN_ + c], w[c * 4 + k], acc);
    }
    u[idx] = acc / (1.f + __expf(-acc));   // silu
}

// ---------------------------------------------------------------------------
// Fused selective scan.
//   grid: (DIN/16, B), block 256 threads (8 warps).
//   Each warp: 2 d-channels; lanes 0-15 -> (d0, n), lanes 16-31 -> (d1, n).
//   h[l] = exp(delta*A_n)*h[l-1] + delta*B*u ; y = (sum_n h*C + u*D) * gate
// ---------------------------------------------------------------------------
__global__ void scan_kernel(const float* __restrict__ delta,
                            const float* __restrict__ u,
                            const float* __restrict__ xdbl,
                            const float* __restrict__ gate,
                            const float* __restrict__ A_log,
                            const float* __restrict__ Dv,
                            float* __restrict__ ys)
{
    constexpr int CH = 64;
    __shared__ float sD[CH][16];
    __shared__ float sU[CH][16];
    __shared__ float sG[CH][16];
    __shared__ float sB[CH][16];
    __shared__ float sC[CH][16];
    __shared__ float sY[CH][16];

    const int b = blockIdx.y;
    const int dbase = blockIdx.x * 16;
    const int tid = threadIdx.x;
    const int warp = tid >> 5;
    const int lane = tid & 31;
    const int half = lane >> 4;       // 0 or 1
    const int n = lane & 15;          // state index
    const int dl = (warp << 1) + half;
    const int d = dbase + dl;

    // A[d][n] = -exp(A_log[d][n]); fold log2(e) for exp2f path
    const float cA = -__expf(A_log[d * NSTATE + n]) * 1.44269504f;
    const float Dd = Dv[d];

    const int li = tid & 15;    // coop-load column
    const int lrow = tid >> 4;  // coop-load row (0..15)

    float h = 0.f;

    for (int c0 = 0; c0 < L_; c0 += CH) {
#pragma unroll
        for (int p = 0; p < CH / 16; p++) {
            const int l = c0 + p * 16 + lrow;
            const size_t t = (size_t)b * L_ + l;
            sD[p * 16 + lrow][li] = delta[t * DIN_ + dbase + li];
            sU[p * 16 + lrow][li] = u[t * DIN_ + dbase + li];
            sG[p * 16 + lrow][li] = gate[t * DIN_ + dbase + li];
            sB[p * 16 + lrow][li] = xdbl[t * 96 + 64 + li];
            sC[p * 16 + lrow][li] = xdbl[t * 96 + 80 + li];
        }
        __syncthreads();

        for (int i = 0; i < CH; i++) {
            const float dlt = sD[i][dl];
            const float uu  = sU[i][dl];
            const float bb  = sB[i][n];
            const float cc  = sC[i][n];
            const float dA  = exp2f(dlt * cA);
            const float dBu = dlt * bb * uu;
            h = fmaf(dA, h, dBu);
            float py = h * cc;
            py += __shfl_xor_sync(0xffffffffu, py, 1);
            py += __shfl_xor_sync(0xffffffffu, py, 2);
            py += __shfl_xor_sync(0xffffffffu, py, 4);
            py += __shfl_xor_sync(0xffffffffu, py, 8);
            if (n == 0)
                sY[i][dl] = (py + uu * Dd) * sG[i][dl];
        }
        __syncthreads();

#pragma unroll
        for (int p = 0; p < CH / 16; p++) {
            const int l = c0 + p * 16 + lrow;
            ys[((size_t)b * L_ + l) * DIN_ + dbase + li] = sY[p * 16 + lrow][li];
        }
        __syncthreads();
    }
}

// ---------------------------------------------------------------------------
extern "C" void kernel_launch(void* const* d_in, const int* in_sizes, int n_in,
                              void* d_out, int out_size)
{
    const float* x      = (const float*)d_in[0];
    const float* W_in   = (const float*)d_in[1];
    const float* conv_w = (const float*)d_in[2];
    const float* conv_b = (const float*)d_in[3];
    const float* W_x    = (const float*)d_in[4];
    const float* W_dt   = (const float*)d_in[5];
    const float* b_dt   = (const float*)d_in[6];
    const float* W_out  = (const float*)d_in[7];
    const float* A_log  = (const float*)d_in[8];
    const float* Dv     = (const float*)d_in[9];
    float* out = (float*)d_out;

    float *xs, *gate, *u, *xdbl, *delta, *ys;
    cudaGetSymbolAddress((void**)&xs,    g_xs);
    cudaGetSymbolAddress((void**)&gate,  g_gate);
    cudaGetSymbolAddress((void**)&u,     g_u);
    cudaGetSymbolAddress((void**)&xdbl,  g_xdbl);
    cudaGetSymbolAddress((void**)&delta, g_delta);
    cudaGetSymbolAddress((void**)&ys,    g_ys);

    // G1: xr = x @ W_in -> split into xs / silu(res)
    gemm64<1><<<dim3(2 * DIN_ / 64, TOKENS / 64), 256>>>(
        x, DIM_, W_in, 2 * DIN_, TOKENS, 2 * DIN_, DIM_,
        nullptr, xs, gate, 0);

    // Depthwise causal conv + SiLU -> u
    conv_silu_kernel<<<(TOKENS * DIN_) / 256, 256>>>(xs, conv_w, conv_b, u);

    // G3: x_dbl = u @ W_x  (N=96)
    gemm64<0><<<dim3(2, TOKENS / 64), 256>>>(
        u, DIN_, W_x, 96, TOKENS, 96, DIN_,
        nullptr, xdbl, nullptr, 96);

    // G4: delta = softplus(x_dbl[:, :64] @ W_dt + b_dt)
    gemm64<2><<<dim3(DIN_ / 64, TOKENS / 64), 256>>>(
        xdbl, 96, W_dt, DIN_, TOKENS, DIN_, DTR_,
        b_dt, delta, nullptr, DIN_);

    // Fused scan -> ys (already gated)
    scan_kernel<<<dim3(DIN_ / 16, B_), 256>>>(
        delta, u, xdbl, gate, A_log, Dv, ys);

    // G6: out = ys @ W_out
    gemm64<0><<<dim3(DIM_ / 64, TOKENS / 64), 256>>>(
        ys, DIN_, W_out, DIM_, TOKENS, DIM_, DIN_,
        nullptr, out, nullptr, DIM_);
}

// round 5
// speedup vs baseline: 2.1874x; 2.1874x over previous
#include <cuda_runtime.h>
#include <cuda_bf16.h>
#include <math.h>
#include <stdint.h>

// Problem constants
#define B_ 2
#define L_ 2048
#define DIM_ 1024
#define DIN_ 2048
#define NSTATE 16
#define DTR_ 64
#define TOKENS (B_ * L_)   // 4096
#define SPLITK 8

// ---------------------------------------------------------------------------
// Scratch buffers (allocation-free: __device__ globals)
// ---------------------------------------------------------------------------
__device__ float g_xs[TOKENS * DIN_];     // conv input
__device__ float g_gate[TOKENS * DIN_];   // silu(res)
__device__ float g_u[TOKENS * DIN_];      // silu(conv(xs))
__device__ float g_xdbl[TOKENS * 96];     // u @ W_x
__device__ float g_xdbl_part[SPLITK * TOKENS * 96]; // split-K partials
__device__ float g_delta[TOKENS * DIN_];  // softplus(...)
__device__ float g_ys[TOKENS * DIN_];     // scan output * gate
// K-major (transposed) weights
__device__ float g_wt_in[2 * DIN_ * DIM_];   // [4096][1024]
__device__ float g_wt_x[96 * DIN_];          // [96][2048]
__device__ float g_wt_dt[DIN_ * DTR_];       // [2048][64]
__device__ float g_wt_out[DIM_ * DIN_];      // [1024][2048]

// ---------------------------------------------------------------------------
__device__ __forceinline__ uint32_t f2tf32(float f) {
    uint32_t u;
    asm("cvt.rna.tf32.f32 %0, %1;" : "=r"(u) : "f"(f));
    return u;
}

__device__ __forceinline__ void mma16n8k8(float* d, const uint32_t* a,
                                          const uint32_t* b) {
    asm volatile(
        "mma.sync.aligned.m16n8k8.row.col.f32.tf32.tf32.f32 "
        "{%0,%1,%2,%3}, {%4,%5,%6,%7}, {%8,%9}, {%0,%1,%2,%3};"
        : "+f"(d[0]), "+f"(d[1]), "+f"(d[2]), "+f"(d[3])
        : "r"(a[0]), "r"(a[1]), "r"(a[2]), "r"(a[3]),
          "r"(b[0]), "r"(b[1]));
}

// ---------------------------------------------------------------------------
// Weight transpose: out[C][R] = in[R][C]
// ---------------------------------------------------------------------------
__global__ void transpose_k(const float* __restrict__ in,
                            float* __restrict__ out, int R, int C)
{
    __shared__ float t[32][33];
    const int bx = blockIdx.x * 32, by = blockIdx.y * 32;
    const int x = threadIdx.x, y0 = threadIdx.y;
#pragma unroll
    for (int i = 0; i < 32; i += 8)
        t[y0 + i][x] = in[(size_t)(by + y0 + i) * C + bx + x];
    __syncthreads();
#pragma unroll
    for (int i = 0; i < 32; i += 8)
        out[(size_t)(bx + y0 + i) * R + by + x] = t[x][y0 + i];
}

// ---------------------------------------------------------------------------
// Deterministic split-K reduction: xdbl = sum_z part[z]
// ---------------------------------------------------------------------------
__global__ void reduce_splitk(const float* __restrict__ part,
                              float* __restrict__ out)
{
    const int idx = blockIdx.x * blockDim.x + threadIdx.x;
    if (idx >= TOKENS * 96) return;
    float s = 0.f;
#pragma unroll
    for (int z = 0; z < SPLITK; z++)
        s += part[(size_t)z * TOKENS * 96 + idx];
    out[idx] = s;
}

// ---------------------------------------------------------------------------
// tf32 mma.sync GEMM: C[M,N] = A[M,K] @ Bt[N,K]^T
//   BM=BN=128, BK=32, 256 threads (2x4 warps, warp tile 64x32).
//   smem tiles: [128][36] f32 (tf32 bits), conflict-free fragment loads.
//   blockIdx.z = split-K slice (EPI==3: write partials to private slab).
// EPI: 0 plain, 1 split (xs / silu->gate), 2 bias+softplus,
//      3 split-K partial store with N guard (slab stride TOKENS*96)
// ---------------------------------------------------------------------------
template <int EPI>
__global__ void __launch_bounds__(256)
gemm_mma(const float* __restrict__ A, int lda,
         const float* __restrict__ Bt, int ldb,
         int N, int K,
         const float* __restrict__ bias,
         float* __restrict__ C0, float* __restrict__ C1, int ldc)
{
    constexpr int BM = 128, BN = 128, BK = 32;
    constexpr int SROW = 36;      // padded row stride (floats)
    constexpr bool NG = (EPI == 3);

    __shared__ uint32_t As[BM * SROW];
    __shared__ uint32_t Bs[BN * SROW];

    const int tid = threadIdx.x;
    const int wid = tid >> 5;
    const int lane = tid & 31;
    const int gr = lane >> 2;     // groupID (0..7)
    const int tig = lane & 3;     // thread-in-group (0..3)
    const int warp_m = wid >> 2;  // 0..1 -> rows warp_m*64
    const int warp_n = wid & 3;   // 0..3 -> cols warp_n*32

    const int block_row = blockIdx.y * BM;
    const int block_col = blockIdx.x * BN;

    const int KT_total = K >> 5;
    const int kt_per = KT_total / gridDim.z;
    const int kt0 = blockIdx.z * kt_per;
    const int kt_end = kt0 + kt_per;

    const float* Ag = A + (size_t)block_row * lda;
    const float* Bg = Bt + (size_t)block_col * ldb;

    float acc[4][4][4];
#pragma unroll
    for (int i = 0; i < 4; i++)
#pragma unroll
        for (int j = 0; j < 4; j++)
#pragma unroll
            for (int e = 0; e < 4; e++) acc[i][j][e] = 0.f;

    float4 Ar[4], Br[4];

    // --- stage tile kt0 ---
    {
        const int kcol = kt0 << 5;
#pragma unroll
        for (int i = 0; i < 4; i++) {
            const int l = tid + i * 256;
            const int r = l >> 3, c = (l & 7) << 2;
            Ar[i] = *reinterpret_cast<const float4*>(Ag + (size_t)r * lda + kcol + c);
            if (!NG || block_col + r < N)
                Br[i] = *reinterpret_cast<const float4*>(Bg + (size_t)r * ldb + kcol + c);
            else
                Br[i] = make_float4(0.f, 0.f, 0.f, 0.f);
        }
#pragma unroll
        for (int i = 0; i < 4; i++) {
            const int l = tid + i * 256;
            const int r = l >> 3, c = (l & 7) << 2;
            uint4 ta = make_uint4(f2tf32(Ar[i].x), f2tf32(Ar[i].y),
                                  f2tf32(Ar[i].z), f2tf32(Ar[i].w));
            uint4 tb = make_uint4(f2tf32(Br[i].x), f2tf32(Br[i].y),
                                  f2tf32(Br[i].z), f2tf32(Br[i].w));
            *reinterpret_cast<uint4*>(&As[r * SROW + c]) = ta;
            *reinterpret_cast<uint4*>(&Bs[r * SROW + c]) = tb;
        }
    }
    __syncthreads();

    for (int kt = kt0; kt < kt_end; kt++) {
        // prefetch next tile into registers
        if (kt + 1 < kt_end) {
            const int kcol = (kt + 1) << 5;
#pragma unroll
            for (int i = 0; i < 4; i++) {
                const int l = tid + i * 256;
                const int r = l >> 3, c = (l & 7) << 2;
                Ar[i] = *reinterpret_cast<const float4*>(Ag + (size_t)r * lda + kcol + c);
                if (!NG || block_col + r < N)
                    Br[i] = *reinterpret_cast<const float4*>(Bg + (size_t)r * ldb + kcol + c);
                else
                    Br[i] = make_float4(0.f, 0.f, 0.f, 0.f);
            }
        }

        // compute on current smem tile
        const int arb = warp_m * 64 + gr;
        const int nb = warp_n * 32 + gr;
#pragma unroll
        for (int ka = 0; ka < 4; ka++) {
            const int kk = ka << 3;
            uint32_t af[4][4];
#pragma unroll
            for (int im = 0; im < 4; im++) {
                const int r0 = (arb + im * 16) * SROW + kk + tig;
                af[im][0] = As[r0];
                af[im][1] = As[r0 + 8 * SROW];
                af[im][2] = As[r0 + 4];
                af[im][3] = As[r0 + 8 * SROW + 4];
            }
            uint32_t bf[4][2];
#pragma unroll
            for (int in = 0; in < 4; in++) {
                const int b0 = (nb + in * 8) * SROW + kk + tig;
                bf[in][0] = Bs[b0];
                bf[in][1] = Bs[b0 + 4];
            }
#pragma unroll
            for (int im = 0; im < 4; im++)
#pragma unroll
                for (int in = 0; in < 4; in++)
                    mma16n8k8(acc[im][in], af[im], bf[in]);
        }
        __syncthreads();

        if (kt + 1 < kt_end) {
#pragma unroll
            for (int i = 0; i < 4; i++) {
                const int l = tid + i * 256;
                const int r = l >> 3, c = (l & 7) << 2;
                uint4 ta = make_uint4(f2tf32(Ar[i].x), f2tf32(Ar[i].y),
                                      f2tf32(Ar[i].z), f2tf32(Ar[i].w));
                uint4 tb = make_uint4(f2tf32(Br[i].x), f2tf32(Br[i].y),
                                      f2tf32(Br[i].z), f2tf32(Br[i].w));
                *reinterpret_cast<uint4*>(&As[r * SROW + c]) = ta;
                *reinterpret_cast<uint4*>(&Bs[r * SROW + c]) = tb;
            }
            __syncthreads();
        }
    }

    // --- epilogue ---
    float* C0z = C0;
    if (EPI == 3)
        C0z = C0 + (size_t)blockIdx.z * TOKENS * 96;

#pragma unroll
    for (int im = 0; im < 4; im++) {
        const int r0 = block_row + warp_m * 64 + im * 16 + gr;
#pragma unroll
        for (int in = 0; in < 4; in++) {
            const int c0 = block_col + warp_n * 32 + in * 8 + 2 * tig;
#pragma unroll
            for (int half = 0; half < 2; half++) {
                const int r = r0 + half * 8;
                const float v0 = acc[im][in][2 * half];
                const float v1 = acc[im][in][2 * half + 1];
                if (EPI == 0) {
                    *reinterpret_cast<float2*>(&C0[(size_t)r * ldc + c0]) =
                        make_float2(v0, v1);
                } else if (EPI == 1) {
                    if (block_col < DIN_) {
                        *reinterpret_cast<float2*>(&C0[(size_t)r * DIN_ + c0]) =
                            make_float2(v0, v1);
                    } else {
                        const float s0 = v0 / (1.f + __expf(-v0));
                        const float s1 = v1 / (1.f + __expf(-v1));
                        *reinterpret_cast<float2*>(
                            &C1[(size_t)r * DIN_ + (c0 - DIN_)]) =
                            make_float2(s0, s1);
                    }
                } else if (EPI == 2) {
                    const float t0 = v0 + __ldg(&bias[c0]);
                    const float t1 = v1 + __ldg(&bias[c0 + 1]);
                    const float s0 = (t0 > 20.f) ? t0 : log1pf(__expf(t0));
                    const float s1 = (t1 > 20.f) ? t1 : log1pf(__expf(t1));
                    *reinterpret_cast<float2*>(&C0[(size_t)r * ldc + c0]) =
                        make_float2(s0, s1);
                } else { // EPI == 3: deterministic split-K partial store
                    if (c0 + 1 < N) {
                        *reinterpret_cast<float2*>(&C0z[(size_t)r * ldc + c0]) =
                            make_float2(v0, v1);
                    } else if (c0 < N) {
                        C0z[(size_t)r * ldc + c0] = v0;
                    }
                }
            }
        }
    }
}

// ---------------------------------------------------------------------------
// Depthwise causal conv1d (k=4) + bias + SiLU
// ---------------------------------------------------------------------------
__global__ void conv_silu_kernel(const float* __restrict__ xs,
                                 const float* __restrict__ w,
                                 const float* __restrict__ bias,
                                 float* __restrict__ u)
{
    const int idx = blockIdx.x * blockDim.x + threadIdx.x;
    const int c = idx & (DIN_ - 1);
    const int t = idx >> 11;
    const int l = t & (L_ - 1);
    float acc = bias[c];
#pragma unroll
    for (int k = 0; k < 4; k++) {
        const int lp = l - 3 + k;
        if (lp >= 0)
            acc = fmaf(xs[(size_t)(t - l + lp) * DIN_ + c], w[c * 4 + k], acc);
    }
    u[idx] = acc / (1.f + __expf(-acc));
}

// ---------------------------------------------------------------------------
// Fused selective scan
// ---------------------------------------------------------------------------
__global__ void scan_kernel(const float* __restrict__ delta,
                            const float* __restrict__ u,
                            const float* __restrict__ xdbl,
                            const float* __restrict__ gate,
                            const float* __restrict__ A_log,
                            const float* __restrict__ Dv,
                            float* __restrict__ ys)
{
    constexpr int CH = 64;
    __shared__ float sD[CH][16];
    __shared__ float sU[CH][16];
    __shared__ float sG[CH][16];
    __shared__ float sB[CH][16];
    __shared__ float sC[CH][16];
    __shared__ float sY[CH][16];

    const int b = blockIdx.y;
    const int dbase = blockIdx.x * 16;
    const int tid = threadIdx.x;
    const int warp = tid >> 5;
    const int lane = tid & 31;
    const int half = lane >> 4;
    const int n = lane & 15;
    const int dl = (warp << 1) + half;
    const int d = dbase + dl;

    const float cA = -__expf(A_log[d * NSTATE + n]) * 1.44269504f;
    const float Dd = Dv[d];

    const int li = tid & 15;
    const int lrow = tid >> 4;

    float h = 0.f;

    for (int c0 = 0; c0 < L_; c0 += CH) {
#pragma unroll
        for (int p = 0; p < CH / 16; p++) {
            const int l = c0 + p * 16 + lrow;
            const size_t t = (size_t)b * L_ + l;
            sD[p * 16 + lrow][li] = delta[t * DIN_ + dbase + li];
            sU[p * 16 + lrow][li] = u[t * DIN_ + dbase + li];
            sG[p * 16 + lrow][li] = gate[t * DIN_ + dbase + li];
            sB[p * 16 + lrow][li] = xdbl[t * 96 + 64 + li];
            sC[p * 16 + lrow][li] = xdbl[t * 96 + 80 + li];
        }
        __syncthreads();

        for (int i = 0; i < CH; i++) {
            const float dlt = sD[i][dl];
            const float uu  = sU[i][dl];
            const float bb  = sB[i][n];
            const float cc  = sC[i][n];
            const float dA  = exp2f(dlt * cA);
            const float dBu = dlt * bb * uu;
            h = fmaf(dA, h, dBu);
            float py = h * cc;
            py += __shfl_xor_sync(0xffffffffu, py, 1);
            py += __shfl_xor_sync(0xffffffffu, py, 2);
            py += __shfl_xor_sync(0xffffffffu, py, 4);
            py += __shfl_xor_sync(0xffffffffu, py, 8);
            if (n == 0)
                sY[i][dl] = (py + uu * Dd) * sG[i][dl];
        }
        __syncthreads();

#pragma unroll
        for (int p = 0; p < CH / 16; p++) {
            const int l = c0 + p * 16 + lrow;
            ys[((size_t)b * L_ + l) * DIN_ + dbase + li] = sY[p * 16 + lrow][li];
        }
        __syncthreads();
    }
}

// ---------------------------------------------------------------------------
extern "C" void kernel_launch(void* const* d_in, const int* in_sizes, int n_in,
                              void* d_out, int out_size)
{
    const float* x      = (const float*)d_in[0];
    const float* W_in   = (const float*)d_in[1];
    const float* conv_w = (const float*)d_in[2];
    const float* conv_b = (const float*)d_in[3];
    const float* W_x    = (const float*)d_in[4];
    const float* W_dt   = (const float*)d_in[5];
    const float* b_dt   = (const float*)d_in[6];
    const float* W_out  = (const float*)d_in[7];
    const float* A_log  = (const float*)d_in[8];
    const float* Dv     = (const float*)d_in[9];
    float* out = (float*)d_out;

    float *xs, *gate, *u, *xdbl, *xdbl_part, *delta, *ys;
    float *wt_in, *wt_x, *wt_dt, *wt_out;
    cudaGetSymbolAddress((void**)&xs,        g_xs);
    cudaGetSymbolAddress((void**)&gate,      g_gate);
    cudaGetSymbolAddress((void**)&u,         g_u);
    cudaGetSymbolAddress((void**)&xdbl,      g_xdbl);
    cudaGetSymbolAddress((void**)&xdbl_part, g_xdbl_part);
    cudaGetSymbolAddress((void**)&delta,     g_delta);
    cudaGetSymbolAddress((void**)&ys,        g_ys);
    cudaGetSymbolAddress((void**)&wt_in,     g_wt_in);
    cudaGetSymbolAddress((void**)&wt_x,      g_wt_x);
    cudaGetSymbolAddress((void**)&wt_dt,     g_wt_dt);
    cudaGetSymbolAddress((void**)&wt_out,    g_wt_out);

    // Pre-transpose weights to K-major [N][K]
    transpose_k<<<dim3(2 * DIN_ / 32, DIM_ / 32), dim3(32, 8)>>>(W_in,  wt_in,  DIM_, 2 * DIN_);
    transpose_k<<<dim3(96 / 32, DIN_ / 32),       dim3(32, 8)>>>(W_x,   wt_x,   DIN_, 96);
    transpose_k<<<dim3(DIN_ / 32, DTR_ / 32),     dim3(32, 8)>>>(W_dt,  wt_dt,  DTR_, DIN_);
    transpose_k<<<dim3(DIM_ / 32, DIN_ / 32),     dim3(32, 8)>>>(W_out, wt_out, DIN_, DIM_);

    // G1: xr = x @ W_in -> split into xs / silu(res)
    gemm_mma<1><<<dim3(2 * DIN_ / 128, TOKENS / 128, 1), 256>>>(
        x, DIM_, wt_in, DIM_, 2 * DIN_, DIM_, nullptr, xs, gate, 0);

    // Depthwise causal conv + SiLU -> u
    conv_silu_kernel<<<(TOKENS * DIN_) / 256, 256>>>(xs, conv_w, conv_b, u);

    // G3: x_dbl = u @ W_x (N=96), deterministic split-K=8
    gemm_mma<3><<<dim3(1, TOKENS / 128, SPLITK), 256>>>(
        u, DIN_, wt_x, DIN_, 96, DIN_, nullptr, xdbl_part, nullptr, 96);
    reduce_splitk<<<(TOKENS * 96 + 255) / 256, 256>>>(xdbl_part, xdbl);

    // G4: delta = softplus(x_dbl[:, :64] @ W_dt + b_dt)
    gemm_mma<2><<<dim3(DIN_ / 128, TOKENS / 128, 1), 256>>>(
        xdbl, 96, wt_dt, DTR_, DIN_, DTR_, b_dt, delta, nullptr, DIN_);

    // Fused scan -> ys (already gated)
    scan_kernel<<<dim3(DIN_ / 16, B_), 256>>>(
        delta, u, xdbl, gate, A_log, Dv, ys);

    // G6: out = ys @ W_out
    gemm_mma<0><<<dim3(DIM_ / 128, TOKENS / 128, 1), 256>>>(
        ys, DIN_, wt_out, DIN_, DIM_, DIN_, nullptr, out, nullptr, DIM_);
}

// round 7
// speedup vs baseline: 2.6365x; 1.2053x over previous
#include <cuda_runtime.h>
#include <cuda_bf16.h>
#include <math.h>
#include <stdint.h>

// Problem constants
#define B_ 2
#define L_ 2048
#define DIM_ 1024
#define DIN_ 2048
#define NSTATE 16
#define DTR_ 64
#define TOKENS (B_ * L_)   // 4096
#define SPLITK 8

// ---------------------------------------------------------------------------
// Scratch buffers (allocation-free: __device__ globals)
// ---------------------------------------------------------------------------
__device__ float g_xr[TOKENS * DIM_];     // tf32-rounded x
__device__ float g_xs[TOKENS * DIN_];     // conv input
__device__ float g_gate[TOKENS * DIN_];   // silu(res)
__device__ float g_u[TOKENS * DIN_];      // silu(conv(xs)) exact (scan)
__device__ float g_ur[TOKENS * DIN_];     // tf32-rounded u (G3)
__device__ float g_xdbl[TOKENS * 96];     // u @ W_x exact (scan B/C)
__device__ float g_xdbl_r[TOKENS * 96];   // tf32-rounded (G4 A)
__device__ float g_xdbl_part[SPLITK * TOKENS * 96]; // split-K partials
__device__ float g_delta[TOKENS * DIN_];  // softplus(...)
__device__ float g_ys[TOKENS * DIN_];     // scan output * gate (tf32-rounded)
// K-major (transposed, tf32-rounded) weights
__device__ float g_wt_in[2 * DIN_ * DIM_];   // [4096][1024]
__device__ float g_wt_x[96 * DIN_];          // [96][2048]
__device__ float g_wt_dt[DIN_ * DTR_];       // [2048][64]
__device__ float g_wt_out[DIM_ * DIN_];      // [1024][2048]

// ---------------------------------------------------------------------------
__device__ __forceinline__ uint32_t f2tf32(float f) {
    uint32_t u;
    asm("cvt.rna.tf32.f32 %0, %1;" : "=r"(u) : "f"(f));
    return u;
}
__device__ __forceinline__ float roundtf(float f) {
    return __uint_as_float(f2tf32(f));
}

__device__ __forceinline__ void mma16n8k8(float* d, const uint32_t* a,
                                          const uint32_t* b) {
    asm volatile(
        "mma.sync.aligned.m16n8k8.row.col.f32.tf32.tf32.f32 "
        "{%0,%1,%2,%3}, {%4,%5,%6,%7}, {%8,%9}, {%0,%1,%2,%3};"
        : "+f"(d[0]), "+f"(d[1]), "+f"(d[2]), "+f"(d[3])
        : "r"(a[0]), "r"(a[1]), "r"(a[2]), "r"(a[3]),
          "r"(b[0]), "r"(b[1]));
}

__device__ __forceinline__ void cp16(uint32_t daddr, const void* src, int zfill) {
    asm volatile("cp.async.cg.shared.global [%0], [%1], 16, %2;"
                 :: "r"(daddr), "l"(src), "r"(zfill) : "memory");
}
__device__ __forceinline__ void cp_commit() {
    asm volatile("cp.async.commit_group;" ::: "memory");
}
__device__ __forceinline__ void cp_wait0() {
    asm volatile("cp.async.wait_group 0;" ::: "memory");
}

// ---------------------------------------------------------------------------
// tf32-round elementwise
// ---------------------------------------------------------------------------
__global__ void round_tf32(const float* __restrict__ in,
                           float* __restrict__ out, int n)
{
    const int idx = blockIdx.x * blockDim.x + threadIdx.x;
    if (idx < n) out[idx] = roundtf(in[idx]);
}

// ---------------------------------------------------------------------------
// Weight transpose (+tf32 round): out[C][R] = round(in[R][C])
// ---------------------------------------------------------------------------
__global__ void transpose_k(const float* __restrict__ in,
                            float* __restrict__ out, int R, int C)
{
    __shared__ float t[32][33];
    const int bx = blockIdx.x * 32, by = blockIdx.y * 32;
    const int x = threadIdx.x, y0 = threadIdx.y;
#pragma unroll
    for (int i = 0; i < 32; i += 8)
        t[y0 + i][x] = in[(size_t)(by + y0 + i) * C + bx + x];
    __syncthreads();
#pragma unroll
    for (int i = 0; i < 32; i += 8)
        out[(size_t)(bx + y0 + i) * R + by + x] = roundtf(t[x][y0 + i]);
}

// ---------------------------------------------------------------------------
// Deterministic split-K reduction: xdbl = sum_z part[z]; also rounded copy
// ---------------------------------------------------------------------------
__global__ void reduce_splitk(const float* __restrict__ part,
                              float* __restrict__ out,
                              float* __restrict__ out_r)
{
    const int idx = blockIdx.x * blockDim.x + threadIdx.x;
    if (idx >= TOKENS * 96) return;
    float s = 0.f;
#pragma unroll
    for (int z = 0; z < SPLITK; z++)
        s += part[(size_t)z * TOKENS * 96 + idx];
    out[idx] = s;
    out_r[idx] = roundtf(s);
}

// ---------------------------------------------------------------------------
// tf32 mma.sync GEMM: C[M,N] = A[M,K] @ Bt[N,K]^T
//   BM=BN=128, BK=32, 256 threads (2x4 warps, warp tile 64x32).
//   Pure cp.async double-buffered pipeline; inputs pre-rounded to tf32.
// EPI: 0 plain, 1 split (xs / silu->gate), 2 bias+softplus,
//      3 split-K partial store with N guard (slab stride TOKENS*96)
// ---------------------------------------------------------------------------
template <int EPI>
__global__ void __launch_bounds__(256, 2)
gemm_mma(const float* __restrict__ A, int lda,
         const float* __restrict__ Bt, int ldb,
         int N, int K,
         const float* __restrict__ bias,
         float* __restrict__ C0, float* __restrict__ C1, int ldc)
{
    constexpr int BM = 128, BN = 128;
    constexpr int SROW = 36;      // padded row stride (floats)
    constexpr int TILE = BM * SROW;  // per-buffer tile words
    constexpr bool NG = (EPI == 3);

    extern __shared__ __align__(16) uint32_t dynsmem[];
    uint32_t* As = dynsmem;             // [2][TILE]
    uint32_t* Bs = dynsmem + 2 * TILE;  // [2][TILE]
    const uint32_t as_addr = (uint32_t)__cvta_generic_to_shared(As);
    const uint32_t bs_addr = (uint32_t)__cvta_generic_to_shared(Bs);

    const int tid = threadIdx.x;
    const int wid = tid >> 5;
    const int lane = tid & 31;
    const int gr = lane >> 2;     // groupID (0..7)
    const int tig = lane & 3;     // thread-in-group (0..3)
    const int warp_m = wid >> 2;  // 0..1 -> rows warp_m*64
    const int warp_n = wid & 3;   // 0..3 -> cols warp_n*32

    const int block_row = blockIdx.y * BM;
    const int block_col = blockIdx.x * BN;

    const int KT_total = K >> 5;
    const int kt_per = KT_total / gridDim.z;
    const int kt0 = blockIdx.z * kt_per;
    const int kt_end = kt0 + kt_per;

    const float* Ag = A + (size_t)block_row * lda;
    const float* Bg = Bt + (size_t)block_col * ldb;

    float acc[4][4][4];
#pragma unroll
    for (int i = 0; i < 4; i++)
#pragma unroll
        for (int j = 0; j < 4; j++)
#pragma unroll
            for (int e = 0; e < 4; e++) acc[i][j][e] = 0.f;

    // stage tile kt into buffer sbuf via cp.async
    auto stage = [&](int kt, int sbuf) {
        const int kcol = kt << 5;
        const uint32_t ab = as_addr + (uint32_t)sbuf * TILE * 4;
        const uint32_t bb = bs_addr + (uint32_t)sbuf * TILE * 4;
#pragma unroll
        for (int i = 0; i < 4; i++) {
            const int l = tid + i * 256;
            const int r = l >> 3, c = (l & 7) << 2;
            cp16(ab + (uint32_t)(r * SROW + c) * 4,
                 Ag + (size_t)r * lda + kcol + c, 16);
        }
#pragma unroll
        for (int i = 0; i < 4; i++) {
            const int l = tid + i * 256;
            const int r = l >> 3, c = (l & 7) << 2;
            int zf = 16;
            int rs = r;
            if (NG && block_col + r >= N) { zf = 0; rs = 0; }
            cp16(bb + (uint32_t)(r * SROW + c) * 4,
                 Bg + (size_t)rs * ldb + kcol + c, zf);
        }
        cp_commit();
    };

    // prologue
    stage(kt0, 0);
    cp_wait0();
    __syncthreads();

    const int arb = warp_m * 64 + gr;
    const int nb = warp_n * 32 + gr;

    for (int kt = kt0; kt < kt_end; kt++) {
        const int buf = (kt - kt0) & 1;
        if (kt + 1 < kt_end)
            stage(kt + 1, buf ^ 1);

        const uint32_t* Ab = As + buf * TILE;
        const uint32_t* Bb = Bs + buf * TILE;
#pragma unroll
        for (int ka = 0; ka < 4; ka++) {
            const int kk = ka << 3;
            uint32_t af[4][4];
#pragma unroll
            for (int im = 0; im < 4; im++) {
                const int r0 = (arb + im * 16) * SROW + kk + tig;
                af[im][0] = Ab[r0];
                af[im][1] = Ab[r0 + 8 * SROW];
                af[im][2] = Ab[r0 + 4];
                af[im][3] = Ab[r0 + 8 * SROW + 4];
            }
            uint32_t bf[4][2];
#pragma unroll
            for (int in = 0; in < 4; in++) {
                const int b0 = (nb + in * 8) * SROW + kk + tig;
                bf[in][0] = Bb[b0];
                bf[in][1] = Bb[b0 + 4];
            }
#pragma unroll
            for (int im = 0; im < 4; im++)
#pragma unroll
                for (int in = 0; in < 4; in++)
                    mma16n8k8(acc[im][in], af[im], bf[in]);
        }

        if (kt + 1 < kt_end)
            cp_wait0();
        __syncthreads();
    }

    // --- epilogue ---
    float* C0z = C0;
    if (EPI == 3)
        C0z = C0 + (size_t)blockIdx.z * TOKENS * 96;

#pragma unroll
    for (int im = 0; im < 4; im++) {
        const int r0 = block_row + warp_m * 64 + im * 16 + gr;
#pragma unroll
        for (int in = 0; in < 4; in++) {
            const int c0 = block_col + warp_n * 32 + in * 8 + 2 * tig;
#pragma unroll
            for (int half = 0; half < 2; half++) {
                const int r = r0 + half * 8;
                const float v0 = acc[im][in][2 * half];
                const float v1 = acc[im][in][2 * half + 1];
                if (EPI == 0) {
                    *reinterpret_cast<float2*>(&C0[(size_t)r * ldc + c0]) =
                        make_float2(v0, v1);
                } else if (EPI == 1) {
                    if (block_col < DIN_) {
                        *reinterpret_cast<float2*>(&C0[(size_t)r * DIN_ + c0]) =
                            make_float2(v0, v1);
                    } else {
                        const float s0 = v0 / (1.f + __expf(-v0));
                        const float s1 = v1 / (1.f + __expf(-v1));
                        *reinterpret_cast<float2*>(
                            &C1[(size_t)r * DIN_ + (c0 - DIN_)]) =
                            make_float2(s0, s1);
                    }
                } else if (EPI == 2) {
                    const float t0 = v0 + __ldg(&bias[c0]);
                    const float t1 = v1 + __ldg(&bias[c0 + 1]);
                    const float s0 = (t0 > 20.f) ? t0 : log1pf(__expf(t0));
                    const float s1 = (t1 > 20.f) ? t1 : log1pf(__expf(t1));
                    *reinterpret_cast<float2*>(&C0[(size_t)r * ldc + c0]) =
                        make_float2(s0, s1);
                } else { // EPI == 3: deterministic split-K partial store
                    if (c0 + 1 < N) {
                        *reinterpret_cast<float2*>(&C0z[(size_t)r * ldc + c0]) =
                            make_float2(v0, v1);
                    } else if (c0 < N) {
                        C0z[(size_t)r * ldc + c0] = v0;
                    }
                }
            }
        }
    }
}

// ---------------------------------------------------------------------------
// Depthwise causal conv1d (k=4) + bias + SiLU; writes exact + rounded copies
// ---------------------------------------------------------------------------
__global__ void conv_silu_kernel(const float* __restrict__ xs,
                                 const float* __restrict__ w,
                                 const float* __restrict__ bias,
                                 float* __restrict__ u,
                                 float* __restrict__ ur)
{
    const int idx = blockIdx.x * blockDim.x + threadIdx.x;
    const int c = idx & (DIN_ - 1);
    const int t = idx >> 11;
    const int l = t & (L_ - 1);
    float acc = bias[c];
#pragma unroll
    for (int k = 0; k < 4; k++) {
        const int lp = l - 3 + k;
        if (lp >= 0)
            acc = fmaf(xs[(size_t)(t - l + lp) * DIN_ + c], w[c * 4 + k], acc);
    }
    const float s = acc / (1.f + __expf(-acc));
    u[idx] = s;
    ur[idx] = roundtf(s);
}

// ---------------------------------------------------------------------------
// Fused selective scan (ys written pre-rounded to tf32 for G6)
// ---------------------------------------------------------------------------
__global__ void scan_kernel(const float* __restrict__ delta,
                            const float* __restrict__ u,
                            const float* __restrict__ xdbl,
                            const float* __restrict__ gate,
                            const float* __restrict__ A_log,
                            const float* __restrict__ Dv,
                            float* __restrict__ ys)
{
    constexpr int CH = 64;
    __shared__ float sD[CH][16];
    __shared__ float sU[CH][16];
    __shared__ float sG[CH][16];
    __shared__ float sB[CH][16];
    __shared__ float sC[CH][16];
    __shared__ float sY[CH][16];

    const int b = blockIdx.y;
    const int dbase = blockIdx.x * 16;
    const int tid = threadIdx.x;
    const int warp = tid >> 5;
    const int lane = tid & 31;
    const int half = lane >> 4;
    const int n = lane & 15;
    const int dl = (warp << 1) + half;
    const int d = dbase + dl;

    const float cA = -__expf(A_log[d * NSTATE + n]) * 1.44269504f;
    const float Dd = Dv[d];

    const int li = tid & 15;
    const int lrow = tid >> 4;

    float h = 0.f;

    for (int c0 = 0; c0 < L_; c0 += CH) {
#pragma unroll
        for (int p = 0; p < CH / 16; p++) {
            const int l = c0 + p * 16 + lrow;
            const size_t t = (size_t)b * L_ + l;
            sD[p * 16 + lrow][li] = delta[t * DIN_ + dbase + li];
            sU[p * 16 + lrow][li] = u[t * DIN_ + dbase + li];
            sG[p * 16 + lrow][li] = gate[t * DIN_ + dbase + li];
            sB[p * 16 + lrow][li] = xdbl[t * 96 + 64 + li];
            sC[p * 16 + lrow][li] = xdbl[t * 96 + 80 + li];
        }
        __syncthreads();

        for (int i = 0; i < CH; i++) {
            const float dlt = sD[i][dl];
            const float uu  = sU[i][dl];
            const float bb  = sB[i][n];
            const float cc  = sC[i][n];
            const float dA  = exp2f(dlt * cA);
            const float dBu = dlt * bb * uu;
            h = fmaf(dA, h, dBu);
            float py = h * cc;
            py += __shfl_xor_sync(0xffffffffu, py, 1);
            py += __shfl_xor_sync(0xffffffffu, py, 2);
            py += __shfl_xor_sync(0xffffffffu, py, 4);
            py += __shfl_xor_sync(0xffffffffu, py, 8);
            if (n == 0)
                sY[i][dl] = (py + uu * Dd) * sG[i][dl];
        }
        __syncthreads();

#pragma unroll
        for (int p = 0; p < CH / 16; p++) {
            const int l = c0 + p * 16 + lrow;
            ys[((size_t)b * L_ + l) * DIN_ + dbase + li] =
                roundtf(sY[p * 16 + lrow][li]);
        }
        __syncthreads();
    }
}

// ---------------------------------------------------------------------------
extern "C" void kernel_launch(void* const* d_in, const int* in_sizes, int n_in,
                              void* d_out, int out_size)
{
    const float* x      = (const float*)d_in[0];
    const float* W_in   = (const float*)d_in[1];
    const float* conv_w = (const float*)d_in[2];
    const float* conv_b = (const float*)d_in[3];
    const float* W_x    = (const float*)d_in[4];
    const float* W_dt   = (const float*)d_in[5];
    const float* b_dt   = (const float*)d_in[6];
    const float* W_out  = (const float*)d_in[7];
    const float* A_log  = (const float*)d_in[8];
    const float* Dv     = (const float*)d_in[9];
    float* out = (float*)d_out;

    float *xr, *xs, *gate, *u, *ur, *xdbl, *xdbl_r, *xdbl_part, *delta, *ys;
    float *wt_in, *wt_x, *wt_dt, *wt_out;
    cudaGetSymbolAddress((void**)&xr,        g_xr);
    cudaGetSymbolAddress((void**)&xs,        g_xs);
    cudaGetSymbolAddress((void**)&gate,      g_gate);
    cudaGetSymbolAddress((void**)&u,         g_u);
    cudaGetSymbolAddress((void**)&ur,        g_ur);
    cudaGetSymbolAddress((void**)&xdbl,      g_xdbl);
    cudaGetSymbolAddress((void**)&xdbl_r,    g_xdbl_r);
    cudaGetSymbolAddress((void**)&xdbl_part, g_xdbl_part);
    cudaGetSymbolAddress((void**)&delta,     g_delta);
    cudaGetSymbolAddress((void**)&ys,        g_ys);
    cudaGetSymbolAddress((void**)&wt_in,     g_wt_in);
    cudaGetSymbolAddress((void**)&wt_x,      g_wt_x);
    cudaGetSymbolAddress((void**)&wt_dt,     g_wt_dt);
    cudaGetSymbolAddress((void**)&wt_out,    g_wt_out);

    constexpr int SMEM = 2 * 2 * 128 * 36 * 4;  // 73728 bytes
    cudaFuncSetAttribute(gemm_mma<0>, cudaFuncAttributeMaxDynamicSharedMemorySize, SMEM);
    cudaFuncSetAttribute(gemm_mma<1>, cudaFuncAttributeMaxDynamicSharedMemorySize, SMEM);
    cudaFuncSetAttribute(gemm_mma<2>, cudaFuncAttributeMaxDynamicSharedMemorySize, SMEM);
    cudaFuncSetAttribute(gemm_mma<3>, cudaFuncAttributeMaxDynamicSharedMemorySize, SMEM);

    // Pre-round x; pre-transpose (and pre-round) weights to K-major [N][K]
    round_tf32<<<(TOKENS * DIM_ + 255) / 256, 256>>>(x, xr, TOKENS * DIM_);
    transpose_k<<<dim3(2 * DIN_ / 32, DIM_ / 32), dim3(32, 8)>>>(W_in,  wt_in,  DIM_, 2 * DIN_);
    transpose_k<<<dim3(96 / 32, DIN_ / 32),       dim3(32, 8)>>>(W_x,   wt_x,   DIN_, 96);
    transpose_k<<<dim3(DIN_ / 32, DTR_ / 32),     dim3(32, 8)>>>(W_dt,  wt_dt,  DTR_, DIN_);
    transpose_k<<<dim3(DIM_ / 32, DIN_ / 32),     dim3(32, 8)>>>(W_out, wt_out, DIN_, DIM_);

    // G1: xr @ W_in -> split into xs / silu(res)
    gemm_mma<1><<<dim3(2 * DIN_ / 128, TOKENS / 128, 1), 256, SMEM>>>(
        xr, DIM_, wt_in, DIM_, 2 * DIN_, DIM_, nullptr, xs, gate, 0);

    // Depthwise causal conv + SiLU -> u (exact) + ur (rounded)
    conv_silu_kernel<<<(TOKENS * DIN_) / 256, 256>>>(xs, conv_w, conv_b, u, ur);

    // G3: x_dbl = u @ W_x (N=96), deterministic split-K=8
    gemm_mma<3><<<dim3(1, TOKENS / 128, SPLITK), 256, SMEM>>>(
        ur, DIN_, wt_x, DIN_, 96, DIN_, nullptr, xdbl_part, nullptr, 96);
    reduce_splitk<<<(TOKENS * 96 + 255) / 256, 256>>>(xdbl_part, xdbl, xdbl_r);

    // G4: delta = softplus(x_dbl[:, :64] @ W_dt + b_dt)
    gemm_mma<2><<<dim3(DIN_ / 128, TOKENS / 128, 1), 256, SMEM>>>(
        xdbl_r, 96, wt_dt, DTR_, DIN_, DTR_, b_dt, delta, nullptr, DIN_);

    // Fused scan -> ys (already gated, pre-rounded for G6)
    scan_kernel<<<dim3(DIN_ / 16, B_), 256>>>(
        delta, u, xdbl, gate, A_log, Dv, ys);

    // G6: out = ys @ W_out
    gemm_mma<0><<<dim3(DIM_ / 128, TOKENS / 128, 1), 256, SMEM>>>(
        ys, DIN_, wt_out, DIN_, DIM_, DIN_, nullptr, out, nullptr, DIM_);
}